// round 5
// baseline (speedup 1.0000x reference)
#include <cuda_runtime.h>
#include <cuda_bf16.h>
#include <math.h>

// Problem constants
#define NTOK 4096
#define DDIM 1024
#define FDIM 4096

// -------- scratch (device globals; no allocation allowed) --------
__device__ float g_Q[NTOK * DDIM];
__device__ float g_K[NTOK * DDIM];
__device__ float g_V[NTOK * DDIM];
__device__ float g_S[(size_t)NTOK * NTOK];
__device__ float g_X[NTOK * DDIM];
__device__ float g_H[(size_t)NTOK * FDIM];

// ================= SGEMM NN: C[M,N] = A[M,K] @ B[K,N] (+bias)(+relu) ========
// 128x128 block tile, BK=8, 256 threads, 8x8 per thread.
// Double-buffered smem: prefetch next k-slice into registers during compute,
// one __syncthreads per k-iteration.
// CAUSAL_K: limit k loop to min(K, blockRowStart+128) -- valid when A's row i
// is zero beyond column i (post-softmax attention matrix).
template <int DO_RELU, int DO_BIAS, int CAUSAL_K>
__global__ __launch_bounds__(256, 2)
void sgemm_nn(int M, int N, int K,
              const float* __restrict__ A,
              const float* __restrict__ B,
              const float* __restrict__ bias,
              float* __restrict__ C)
{
    const int bm = blockIdx.y * 128;
    const int bn = blockIdx.x * 128;
    int kEnd = K;
    if (CAUSAL_K) kEnd = min(K, bm + 128);

    __shared__ float As[2][8][128];
    __shared__ float Bs[2][8][128];

    const int tid  = threadIdx.x;
    const int aRow = tid >> 1;          // 0..127
    const int aCol = (tid & 1) << 2;    // 0 or 4
    const int bRow = tid >> 5;          // 0..7
    const int bCol = (tid & 31) << 2;   // 0..124

    const int tx = tid & 15;
    const int ty = tid >> 4;

    float acc[8][8];
#pragma unroll
    for (int i = 0; i < 8; i++)
#pragma unroll
        for (int j = 0; j < 8; j++) acc[i][j] = 0.f;

    const float* Aptr = A + (size_t)(bm + aRow) * K + aCol;
    const float* Bptr = B + (size_t)bRow * N + bn + bCol;

    // preload k0 = 0 into buffer 0
    {
        float4 a = *(const float4*)(Aptr);
        As[0][aCol + 0][aRow] = a.x;
        As[0][aCol + 1][aRow] = a.y;
        As[0][aCol + 2][aRow] = a.z;
        As[0][aCol + 3][aRow] = a.w;
        float4 b = *(const float4*)(Bptr);
        *(float4*)&Bs[0][bRow][bCol] = b;
    }
    __syncthreads();

    int buf = 0;
    for (int k0 = 0; k0 < kEnd; k0 += 8) {
        const bool has_next = (k0 + 8) < kEnd;
        float4 an, bn4;
        if (has_next) {
            an  = *(const float4*)(Aptr + (k0 + 8));
            bn4 = *(const float4*)(Bptr + (size_t)(k0 + 8) * N);
        }
#pragma unroll
        for (int k = 0; k < 8; k++) {
            float4 ra0 = *(const float4*)&As[buf][k][ty * 8];
            float4 ra1 = *(const float4*)&As[buf][k][ty * 8 + 4];
            float4 rb0 = *(const float4*)&Bs[buf][k][tx * 8];
            float4 rb1 = *(const float4*)&Bs[buf][k][tx * 8 + 4];
            float ra[8] = {ra0.x, ra0.y, ra0.z, ra0.w, ra1.x, ra1.y, ra1.z, ra1.w};
            float rb[8] = {rb0.x, rb0.y, rb0.z, rb0.w, rb1.x, rb1.y, rb1.z, rb1.w};
#pragma unroll
            for (int i = 0; i < 8; i++)
#pragma unroll
                for (int j = 0; j < 8; j++)
                    acc[i][j] = fmaf(ra[i], rb[j], acc[i][j]);
        }
        if (has_next) {
            const int nb = buf ^ 1;
            As[nb][aCol + 0][aRow] = an.x;
            As[nb][aCol + 1][aRow] = an.y;
            As[nb][aCol + 2][aRow] = an.z;
            As[nb][aCol + 3][aRow] = an.w;
            *(float4*)&Bs[nb][bRow][bCol] = bn4;
            __syncthreads();
        }
        buf ^= 1;
    }

#pragma unroll
    for (int i = 0; i < 8; i++) {
        const int row = bm + ty * 8 + i;
#pragma unroll
        for (int j = 0; j < 8; j += 4) {
            const int col = bn + tx * 8 + j;
            float4 v = make_float4(acc[i][j], acc[i][j + 1], acc[i][j + 2], acc[i][j + 3]);
            if (DO_BIAS) {
                v.x += bias[col];     v.y += bias[col + 1];
                v.z += bias[col + 2]; v.w += bias[col + 3];
            }
            if (DO_RELU) {
                v.x = fmaxf(v.x, 0.f); v.y = fmaxf(v.y, 0.f);
                v.z = fmaxf(v.z, 0.f); v.w = fmaxf(v.w, 0.f);
            }
            *(float4*)(C + (size_t)row * N + col) = v;
        }
    }
}

// ============ SGEMM NT (scores): S[M,M] = (Q[M,D] @ K[M,D]^T) * inv_scale ===
// Skips tiles fully above the causal diagonal (never read by softmax).
// Same double-buffered pipeline.
__global__ __launch_bounds__(256, 2)
void sgemm_nt_scores(int M, int D,
                     const float* __restrict__ Q,
                     const float* __restrict__ Km,
                     float* __restrict__ S,
                     float inv_scale)
{
    const int bm = blockIdx.y * 128;
    const int bn = blockIdx.x * 128;
    if (bn > bm + 127) return;  // fully masked tile

    __shared__ float As[2][8][128];
    __shared__ float Bs[2][8][128];

    const int tid  = threadIdx.x;
    const int aRow = tid >> 1;
    const int aCol = (tid & 1) << 2;
    const int tx = tid & 15;
    const int ty = tid >> 4;

    float acc[8][8];
#pragma unroll
    for (int i = 0; i < 8; i++)
#pragma unroll
        for (int j = 0; j < 8; j++) acc[i][j] = 0.f;

    const float* Qptr = Q  + (size_t)(bm + aRow) * D + aCol;
    const float* Kptr = Km + (size_t)(bn + aRow) * D + aCol;

    {
        float4 a = *(const float4*)(Qptr);
        As[0][aCol + 0][aRow] = a.x;
        As[0][aCol + 1][aRow] = a.y;
        As[0][aCol + 2][aRow] = a.z;
        As[0][aCol + 3][aRow] = a.w;
        float4 b = *(const float4*)(Kptr);
        Bs[0][aCol + 0][aRow] = b.x;
        Bs[0][aCol + 1][aRow] = b.y;
        Bs[0][aCol + 2][aRow] = b.z;
        Bs[0][aCol + 3][aRow] = b.w;
    }
    __syncthreads();

    int buf = 0;
    for (int k0 = 0; k0 < D; k0 += 8) {
        const bool has_next = (k0 + 8) < D;
        float4 an, bn4;
        if (has_next) {
            an  = *(const float4*)(Qptr + (k0 + 8));
            bn4 = *(const float4*)(Kptr + (k0 + 8));
        }
#pragma unroll
        for (int k = 0; k < 8; k++) {
            float4 ra0 = *(const float4*)&As[buf][k][ty * 8];
            float4 ra1 = *(const float4*)&As[buf][k][ty * 8 + 4];
            float4 rb0 = *(const float4*)&Bs[buf][k][tx * 8];
            float4 rb1 = *(const float4*)&Bs[buf][k][tx * 8 + 4];
            float ra[8] = {ra0.x, ra0.y, ra0.z, ra0.w, ra1.x, ra1.y, ra1.z, ra1.w};
            float rb[8] = {rb0.x, rb0.y, rb0.z, rb0.w, rb1.x, rb1.y, rb1.z, rb1.w};
#pragma unroll
            for (int i = 0; i < 8; i++)
#pragma unroll
                for (int j = 0; j < 8; j++)
                    acc[i][j] = fmaf(ra[i], rb[j], acc[i][j]);
        }
        if (has_next) {
            const int nb = buf ^ 1;
            As[nb][aCol + 0][aRow] = an.x;
            As[nb][aCol + 1][aRow] = an.y;
            As[nb][aCol + 2][aRow] = an.z;
            As[nb][aCol + 3][aRow] = an.w;
            Bs[nb][aCol + 0][aRow] = bn4.x;
            Bs[nb][aCol + 1][aRow] = bn4.y;
            Bs[nb][aCol + 2][aRow] = bn4.z;
            Bs[nb][aCol + 3][aRow] = bn4.w;
            __syncthreads();
        }
        buf ^= 1;
    }

#pragma unroll
    for (int i = 0; i < 8; i++) {
        const int row = bm + ty * 8 + i;
#pragma unroll
        for (int j = 0; j < 8; j += 4) {
            const int col = bn + tx * 8 + j;
            float4 v = make_float4(acc[i][j]     * inv_scale,
                                   acc[i][j + 1] * inv_scale,
                                   acc[i][j + 2] * inv_scale,
                                   acc[i][j + 3] * inv_scale);
            *(float4*)(S + (size_t)row * M + col) = v;
        }
    }
}

// ================= causal softmax: row i uses cols [0, i]; zeros beyond =====
// Row values cached in registers (<= 16 per thread): one GMEM read, one write.
__global__ __launch_bounds__(256)
void causal_softmax(float* __restrict__ S, int N)
{
    const int i   = blockIdx.x;
    const int L   = i + 1;
    float* row    = S + (size_t)i * N;
    const int tid = threadIdx.x;
    const int lane = tid & 31, wid = tid >> 5;

    __shared__ float sred[8];

    // load into registers
    float v[16];
    int cnt = 0;
    for (int j = tid; j < L; j += 256) v[cnt++] = row[j];

    // max
    float m = -1e30f;
    for (int t = 0; t < cnt; t++) m = fmaxf(m, v[t]);
#pragma unroll
    for (int o = 16; o > 0; o >>= 1) m = fmaxf(m, __shfl_xor_sync(0xffffffffu, m, o));
    if (lane == 0) sred[wid] = m;
    __syncthreads();
    if (tid < 32) {
        float r = (tid < 8) ? sred[tid] : -1e30f;
#pragma unroll
        for (int o = 4; o > 0; o >>= 1) r = fmaxf(r, __shfl_xor_sync(0xffffffffu, r, o));
        if (tid == 0) sred[0] = r;
    }
    __syncthreads();
    m = sred[0];
    __syncthreads();

    // exp + sum
    float s = 0.f;
    for (int t = 0; t < cnt; t++) { v[t] = __expf(v[t] - m); s += v[t]; }
#pragma unroll
    for (int o = 16; o > 0; o >>= 1) s += __shfl_xor_sync(0xffffffffu, s, o);
    if (lane == 0) sred[wid] = s;
    __syncthreads();
    if (tid < 32) {
        float r = (tid < 8) ? sred[tid] : 0.f;
#pragma unroll
        for (int o = 4; o > 0; o >>= 1) r += __shfl_xor_sync(0xffffffffu, r, o);
        if (tid == 0) sred[0] = r;
    }
    __syncthreads();
    const float inv = 1.0f / sred[0];

    // write normalized probs; zero the masked region
    {
        int t = 0;
        for (int j = tid; j < L; j += 256) row[j] = v[t++] * inv;
    }
    for (int j = L + tid; j < N; j += 256) row[j] = 0.f;
}

// ================= add + LayerNorm (D = 1024, 256 threads, 4 elems/thread) ==
__global__ __launch_bounds__(256)
void add_layernorm(const float* __restrict__ attn,
                   const float* __restrict__ emb,
                   const float* __restrict__ gamma,
                   const float* __restrict__ beta,
                   float* __restrict__ out)
{
    const int i   = blockIdx.x;
    const int tid = threadIdx.x;
    const int lane = tid & 31, wid = tid >> 5;
    const int off = i * DDIM + tid * 4;

    float4 a = *(const float4*)(attn + off);
    float4 e = *(const float4*)(emb + off);
    float v0 = a.x + e.x, v1 = a.y + e.y, v2 = a.z + e.z, v3 = a.w + e.w;

    __shared__ float s_sum[8], s_sq[8];

    float sum = v0 + v1 + v2 + v3;
    float sq  = v0 * v0 + v1 * v1 + v2 * v2 + v3 * v3;
#pragma unroll
    for (int o = 16; o > 0; o >>= 1) {
        sum += __shfl_xor_sync(0xffffffffu, sum, o);
        sq  += __shfl_xor_sync(0xffffffffu, sq, o);
    }
    if (lane == 0) { s_sum[wid] = sum; s_sq[wid] = sq; }
    __syncthreads();
    if (tid < 32) {
        float r1 = (tid < 8) ? s_sum[tid] : 0.f;
        float r2 = (tid < 8) ? s_sq[tid]  : 0.f;
#pragma unroll
        for (int o = 4; o > 0; o >>= 1) {
            r1 += __shfl_xor_sync(0xffffffffu, r1, o);
            r2 += __shfl_xor_sync(0xffffffffu, r2, o);
        }
        if (tid == 0) { s_sum[0] = r1; s_sq[0] = r2; }
    }
    __syncthreads();
    const float mu   = s_sum[0] * (1.0f / DDIM);
    const float var  = s_sq[0] * (1.0f / DDIM) - mu * mu;
    const float rstd = rsqrtf(var + 1e-5f);

    const int c = tid * 4;
    float4 g = *(const float4*)(gamma + c);
    float4 b = *(const float4*)(beta + c);
    float4 o4;
    o4.x = (v0 - mu) * rstd * g.x + b.x;
    o4.y = (v1 - mu) * rstd * g.y + b.y;
    o4.z = (v2 - mu) * rstd * g.z + b.z;
    o4.w = (v3 - mu) * rstd * g.w + b.w;
    *(float4*)(out + off) = o4;
}

// ============================================================================
extern "C" void kernel_launch(void* const* d_in, const int* in_sizes, int n_in,
                              void* d_out, int out_size)
{
    const float* emb   = (const float*)d_in[0];
    const float* Wq    = (const float*)d_in[1];
    const float* bq    = (const float*)d_in[2];
    const float* Wk    = (const float*)d_in[3];
    const float* bk    = (const float*)d_in[4];
    const float* Wv    = (const float*)d_in[5];
    const float* bv    = (const float*)d_in[6];
    const float* gamma = (const float*)d_in[7];
    const float* beta  = (const float*)d_in[8];
    const float* W1    = (const float*)d_in[9];
    const float* b1    = (const float*)d_in[10];
    const float* W2    = (const float*)d_in[11];
    const float* b2    = (const float*)d_in[12];
    float* out = (float*)d_out;

    float *Q, *K, *V, *S, *X, *H;
    cudaGetSymbolAddress((void**)&Q, g_Q);
    cudaGetSymbolAddress((void**)&K, g_K);
    cudaGetSymbolAddress((void**)&V, g_V);
    cudaGetSymbolAddress((void**)&S, g_S);
    cudaGetSymbolAddress((void**)&X, g_X);
    cudaGetSymbolAddress((void**)&H, g_H);

    const dim3 blk(256);
    const dim3 grid_nd(DDIM / 128, NTOK / 128);   // (8, 32)  for [4096,1024] outputs
    const dim3 grid_nn(NTOK / 128, NTOK / 128);   // (32, 32) for [4096,4096] outputs

    // QKV projections
    sgemm_nn<0, 1, 0><<<grid_nd, blk>>>(NTOK, DDIM, DDIM, emb, Wq, bq, Q);
    sgemm_nn<0, 1, 0><<<grid_nd, blk>>>(NTOK, DDIM, DDIM, emb, Wk, bk, K);
    sgemm_nn<0, 1, 0><<<grid_nd, blk>>>(NTOK, DDIM, DDIM, emb, Wv, bv, V);

    // attention scores (causal tiles only) + softmax
    sgemm_nt_scores<<<grid_nn, blk>>>(NTOK, DDIM, Q, K, S, 1.0f / 32.0f);
    causal_softmax<<<NTOK, blk>>>(S, NTOK);

    // A @ V with causal k-limit
    sgemm_nn<0, 0, 1><<<grid_nd, blk>>>(NTOK, DDIM, NTOK, S, V, nullptr, X);

    // add + layernorm (in place on X)
    add_layernorm<<<NTOK, blk>>>(X, emb, gamma, beta, X);

    // FFN
    sgemm_nn<1, 1, 0><<<grid_nn, blk>>>(NTOK, FDIM, DDIM, X, W1, b1, H);
    sgemm_nn<0, 1, 0><<<grid_nd, blk>>>(NTOK, DDIM, FDIM, H, W2, b2, out);
}

// round 8
// speedup vs baseline: 2.0800x; 2.0800x over previous
#include <cuda_runtime.h>
#include <cuda_bf16.h>
#include <math.h>
#include <stdint.h>

// Problem constants
#define NTOK 4096
#define DDIM 1024
#define FDIM 4096

// -------- scratch (device globals; no allocation allowed) --------
__device__ float g_Q[NTOK * DDIM];
__device__ float g_K[NTOK * DDIM];
__device__ float g_V[NTOK * DDIM];
__device__ float g_S[(size_t)NTOK * NTOK];
__device__ float g_X[NTOK * DDIM];
__device__ float g_H[(size_t)NTOK * FDIM];

// pre-transposed, bf16-split weights ([N,K] K-major) and V^T
__device__ __nv_bfloat16 g_Wqt_h[DDIM * DDIM];
__device__ __nv_bfloat16 g_Wqt_l[DDIM * DDIM];
__device__ __nv_bfloat16 g_Wkt_h[DDIM * DDIM];
__device__ __nv_bfloat16 g_Wkt_l[DDIM * DDIM];
__device__ __nv_bfloat16 g_Wvt_h[DDIM * DDIM];
__device__ __nv_bfloat16 g_Wvt_l[DDIM * DDIM];
__device__ __nv_bfloat16 g_W1t_h[(size_t)FDIM * DDIM];
__device__ __nv_bfloat16 g_W1t_l[(size_t)FDIM * DDIM];
__device__ __nv_bfloat16 g_W2t_h[(size_t)FDIM * DDIM];
__device__ __nv_bfloat16 g_W2t_l[(size_t)FDIM * DDIM];
__device__ __nv_bfloat16 g_Vt_h[(size_t)DDIM * NTOK];
__device__ __nv_bfloat16 g_Vt_l[(size_t)DDIM * NTOK];

// ================= helpers ==================================================
__device__ __forceinline__ uint32_t smem_u32(const void* p) {
    uint32_t a;
    asm("{ .reg .u64 t; cvta.to.shared.u64 t, %1; cvt.u32.u64 %0, t; }"
        : "=r"(a) : "l"(p));
    return a;
}

// split 8 fp32 -> 8 bf16 hi + 8 bf16 lo (packed)
__device__ __forceinline__ void split8(float4 a, float4 b, uint4& h, uint4& l) {
    float f[8] = {a.x, a.y, a.z, a.w, b.x, b.y, b.z, b.w};
    uint32_t hw[4], lw[4];
#pragma unroll
    for (int i = 0; i < 4; i++) {
        __nv_bfloat16 h0 = __float2bfloat16(f[2 * i]);
        __nv_bfloat16 h1 = __float2bfloat16(f[2 * i + 1]);
        __nv_bfloat16 l0 = __float2bfloat16(f[2 * i] - __bfloat162float(h0));
        __nv_bfloat16 l1 = __float2bfloat16(f[2 * i + 1] - __bfloat162float(h1));
        hw[i] = ((uint32_t)__bfloat16_as_ushort(h1) << 16) | (uint32_t)__bfloat16_as_ushort(h0);
        lw[i] = ((uint32_t)__bfloat16_as_ushort(l1) << 16) | (uint32_t)__bfloat16_as_ushort(l0);
    }
    h = make_uint4(hw[0], hw[1], hw[2], hw[3]);
    l = make_uint4(lw[0], lw[1], lw[2], lw[3]);
}

#define LDSM4(d, addr)                                                        \
    asm volatile("ldmatrix.sync.aligned.m8n8.x4.shared.b16 {%0,%1,%2,%3}, [%4];" \
        : "=r"((d)[0]), "=r"((d)[1]), "=r"((d)[2]), "=r"((d)[3]) : "r"(addr))

#define MMA16816(c, a, b)                                                     \
    asm volatile("mma.sync.aligned.m16n8k16.row.col.f32.bf16.bf16.f32 "       \
        "{%0,%1,%2,%3}, {%4,%5,%6,%7}, {%8,%9}, {%0,%1,%2,%3};"               \
        : "+f"((c)[0]), "+f"((c)[1]), "+f"((c)[2]), "+f"((c)[3])              \
        : "r"((a)[0]), "r"((a)[1]), "r"((a)[2]), "r"((a)[3]),                 \
          "r"((b)[0]), "r"((b)[1]))

// smem layout: 4 tiles (Ah, Al, Bh, Bl), 128 rows x 40 bf16 (80B stride), x2 stages
#define ROWB 80
#define TILEB (128 * ROWB)          // 10240
#define SM_TILE(s, t) ((s) * (4 * TILEB) + (t) * TILEB)
#define SM_BYTES (2 * 4 * TILEB)    // 81920

// ================= tensor-core GEMM (mma.sync bf16, 3-term split) ===========
// C[M,N] = A[M,K] @ B^T(K-major) (+bias)(+relu) * out_scale
// B_FP32: B rows fp32 [*,K] split on the fly (scores: B = K matrix)
// else:   B pre-split bf16 [N,K]
// SKIP_UPPER: skip tiles fully above causal diagonal (scores)
// KLIMIT: kEnd = min(K, bm+128) (A@V; A rows zero beyond diagonal)
template <int DO_BIAS, int DO_RELU, int B_FP32, int SKIP_UPPER, int KLIMIT>
__global__ __launch_bounds__(256, 1)
void mma_gemm(int M, int N, int K,
              const float* __restrict__ A,
              const __nv_bfloat16* __restrict__ Bhg,
              const __nv_bfloat16* __restrict__ Blg,
              const float* __restrict__ Bf,
              const float* __restrict__ bias,
              float* __restrict__ C,
              float out_scale)
{
    const int bm = blockIdx.y * 128;
    const int bn = blockIdx.x * 128;
    if (SKIP_UPPER && bn > bm + 127) return;

    extern __shared__ __align__(128) char smem[];
    const uint32_t sb = smem_u32(smem);

    const int tid  = threadIdx.x;
    const int wid  = tid >> 5;
    const int lane = tid & 31;
    const int wm   = wid >> 2;          // 0..1 -> m offset wm*64
    const int wn   = wid & 3;           // 0..3 -> n offset wn*32

    // loader mapping: each thread owns row r, 16-column half
    const int lr   = tid >> 1;          // 0..127
    const int lh   = tid & 1;           // 0 / 1

    int kEnd = K;
    if (KLIMIT) kEnd = min(K, bm + 128);
    const int NC = kEnd >> 5;           // chunks of 32

    float acc[4][4][4];
#pragma unroll
    for (int i = 0; i < 4; i++)
#pragma unroll
        for (int j = 0; j < 4; j++)
#pragma unroll
            for (int q = 0; q < 4; q++) acc[i][j][q] = 0.f;

    const float* Arow = A + (size_t)(bm + lr) * K + lh * 16;

    // ---- tile storers ----
    auto storeA = [&](int s, const float4* rg) {
        uint4 h, l;
        split8(rg[0], rg[1], h, l);
        uint32_t o = (uint32_t)(lr * ROWB + lh * 32);
        *(uint4*)(smem + SM_TILE(s, 0) + o) = h;
        *(uint4*)(smem + SM_TILE(s, 1) + o) = l;
        split8(rg[2], rg[3], h, l);
        *(uint4*)(smem + SM_TILE(s, 0) + o + 16) = h;
        *(uint4*)(smem + SM_TILE(s, 1) + o + 16) = l;
    };
    auto storeBf = [&](int s, const float4* rg) {
        uint4 h, l;
        split8(rg[0], rg[1], h, l);
        uint32_t o = (uint32_t)(lr * ROWB + lh * 32);
        *(uint4*)(smem + SM_TILE(s, 2) + o) = h;
        *(uint4*)(smem + SM_TILE(s, 3) + o) = l;
        split8(rg[2], rg[3], h, l);
        *(uint4*)(smem + SM_TILE(s, 2) + o + 16) = h;
        *(uint4*)(smem + SM_TILE(s, 3) + o + 16) = l;
    };
    auto storeBp = [&](int s, const uint4* rg) {
        uint32_t o = (uint32_t)(lr * ROWB + lh * 32);
        *(uint4*)(smem + SM_TILE(s, 2) + o)      = rg[0];
        *(uint4*)(smem + SM_TILE(s, 2) + o + 16) = rg[1];
        *(uint4*)(smem + SM_TILE(s, 3) + o)      = rg[2];
        *(uint4*)(smem + SM_TILE(s, 3) + o + 16) = rg[3];
    };

    // ---- global loaders into regs ----
    float4 ra[4];                   // A chunk regs
    float4 rbf[4];                  // B fp32 chunk regs
    uint4  rbp[4];                  // B presplit regs (2 hi + 2 lo)

    auto loadA = [&](int k0) {
        const float4* p = (const float4*)(Arow + k0);
        ra[0] = p[0]; ra[1] = p[1]; ra[2] = p[2]; ra[3] = p[3];
    };
    auto loadB = [&](int k0) {
        if (B_FP32) {
            const float4* p = (const float4*)(Bf + (size_t)(bn + lr) * K + k0 + lh * 16);
            rbf[0] = p[0]; rbf[1] = p[1]; rbf[2] = p[2]; rbf[3] = p[3];
        } else {
            const size_t base = (size_t)(bn + lr) * K + k0 + lh * 16;
            const uint4* ph = (const uint4*)(Bhg + base);
            const uint4* pl = (const uint4*)(Blg + base);
            rbp[0] = ph[0]; rbp[1] = ph[1];
            rbp[2] = pl[0]; rbp[3] = pl[1];
        }
    };
    auto storeB = [&](int s) {
        if (B_FP32) storeBf(s, rbf);
        else        storeBp(s, rbp);
    };

    // ---- fragment addresses (per-lane constants except stage/k/tile offsets)
    const uint32_t a_ro = (uint32_t)((wm * 64 + (lane & 7) + ((lane >> 3) & 1) * 8) * ROWB
                                     + (((lane >> 4) & 1) * 8) * 2);
    const uint32_t b_ro = (uint32_t)((wn * 32 + (lane & 7) + ((lane >> 4) & 1) * 8) * ROWB
                                     + (((lane >> 3) & 1) * 8) * 2);

    // preload chunk 0
    loadA(0);
    storeA(0, ra);
    loadB(0);
    storeB(0);
    __syncthreads();

    for (int c = 0; c < NC; c++) {
        const int s = c & 1;
        const bool nxt = (c + 1) < NC;
        if (nxt) { loadA((c + 1) << 5); loadB((c + 1) << 5); }

        // ---- compute chunk c ----
#pragma unroll
        for (int ks = 0; ks < 2; ks++) {
            uint32_t ah[4][4], al[4][4];
#pragma unroll
            for (int mi = 0; mi < 4; mi++) {
                const uint32_t off = a_ro + (uint32_t)(mi * 16 * ROWB + ks * 32);
                LDSM4(ah[mi], sb + SM_TILE(s, 0) + off);
                LDSM4(al[mi], sb + SM_TILE(s, 1) + off);
            }
            uint32_t bh[4][2], bl[4][2];
#pragma unroll
            for (int np = 0; np < 2; np++) {
                const uint32_t off = b_ro + (uint32_t)(np * 16 * ROWB + ks * 32);
                uint32_t t[4];
                LDSM4(t, sb + SM_TILE(s, 2) + off);
                bh[2 * np][0] = t[0]; bh[2 * np][1] = t[1];
                bh[2 * np + 1][0] = t[2]; bh[2 * np + 1][1] = t[3];
                LDSM4(t, sb + SM_TILE(s, 3) + off);
                bl[2 * np][0] = t[0]; bl[2 * np][1] = t[1];
                bl[2 * np + 1][0] = t[2]; bl[2 * np + 1][1] = t[3];
            }
#pragma unroll
            for (int mi = 0; mi < 4; mi++)
#pragma unroll
                for (int ni = 0; ni < 4; ni++) {
                    MMA16816(acc[mi][ni], ah[mi], bh[ni]);
                    MMA16816(acc[mi][ni], ah[mi], bl[ni]);
                    MMA16816(acc[mi][ni], al[mi], bh[ni]);
                }
        }

        if (nxt) {
            storeA(s ^ 1, ra);
            storeB(s ^ 1);
            __syncthreads();
        }
    }

    // ---- epilogue ----
    const int row0 = bm + wm * 64;
    const int col0 = bn + wn * 32;
    const int rl = lane >> 2;           // 0..7
    const int cl = (lane & 3) * 2;      // 0,2,4,6
#pragma unroll
    for (int mi = 0; mi < 4; mi++) {
#pragma unroll
        for (int ni = 0; ni < 4; ni++) {
            const int cc = col0 + ni * 8 + cl;
            float bx = 0.f, by = 0.f;
            if (DO_BIAS) { bx = bias[cc]; by = bias[cc + 1]; }
            float v0 = acc[mi][ni][0] * out_scale + bx;
            float v1 = acc[mi][ni][1] * out_scale + by;
            float v2 = acc[mi][ni][2] * out_scale + bx;
            float v3 = acc[mi][ni][3] * out_scale + by;
            if (DO_RELU) {
                v0 = fmaxf(v0, 0.f); v1 = fmaxf(v1, 0.f);
                v2 = fmaxf(v2, 0.f); v3 = fmaxf(v3, 0.f);
            }
            const int rr = row0 + mi * 16 + rl;
            *(float2*)(C + (size_t)rr * N + cc)       = make_float2(v0, v1);
            *(float2*)(C + (size_t)(rr + 8) * N + cc) = make_float2(v2, v3);
        }
    }
}

// ================= transpose + bf16 split: W[R,C] -> T[C,R] =================
__global__ __launch_bounds__(256)
void transpose_split(const float* __restrict__ W, int R, int C,
                     __nv_bfloat16* __restrict__ Th, __nv_bfloat16* __restrict__ Tl)
{
    __shared__ float t[32][33];
    const int r0 = blockIdx.y * 32;
    const int c0 = blockIdx.x * 32;
    const int tx = threadIdx.x & 31;
    const int ty = threadIdx.x >> 5;   // 0..7
#pragma unroll
    for (int i = 0; i < 4; i++)
        t[ty + 8 * i][tx] = W[(size_t)(r0 + ty + 8 * i) * C + c0 + tx];
    __syncthreads();
#pragma unroll
    for (int i = 0; i < 4; i++) {
        const float v = t[tx][ty + 8 * i];
        const __nv_bfloat16 h = __float2bfloat16(v);
        const __nv_bfloat16 l = __float2bfloat16(v - __bfloat162float(h));
        const size_t o = (size_t)(c0 + ty + 8 * i) * R + r0 + tx;
        Th[o] = h;
        Tl[o] = l;
    }
}

// ================= causal softmax ===========================================
__global__ __launch_bounds__(256)
void causal_softmax(float* __restrict__ S, int N)
{
    const int i   = blockIdx.x;
    const int L   = i + 1;
    float* row    = S + (size_t)i * N;
    const int tid = threadIdx.x;
    const int lane = tid & 31, wid = tid >> 5;

    __shared__ float sred[8];

    float v[16];
    int cnt = 0;
    for (int j = tid; j < L; j += 256) v[cnt++] = row[j];

    float m = -1e30f;
    for (int t = 0; t < cnt; t++) m = fmaxf(m, v[t]);
#pragma unroll
    for (int o = 16; o > 0; o >>= 1) m = fmaxf(m, __shfl_xor_sync(0xffffffffu, m, o));
    if (lane == 0) sred[wid] = m;
    __syncthreads();
    if (tid < 32) {
        float r = (tid < 8) ? sred[tid] : -1e30f;
#pragma unroll
        for (int o = 4; o > 0; o >>= 1) r = fmaxf(r, __shfl_xor_sync(0xffffffffu, r, o));
        if (tid == 0) sred[0] = r;
    }
    __syncthreads();
    m = sred[0];
    __syncthreads();

    float s = 0.f;
    for (int t = 0; t < cnt; t++) { v[t] = __expf(v[t] - m); s += v[t]; }
#pragma unroll
    for (int o = 16; o > 0; o >>= 1) s += __shfl_xor_sync(0xffffffffu, s, o);
    if (lane == 0) sred[wid] = s;
    __syncthreads();
    if (tid < 32) {
        float r = (tid < 8) ? sred[tid] : 0.f;
#pragma unroll
        for (int o = 4; o > 0; o >>= 1) r += __shfl_xor_sync(0xffffffffu, r, o);
        if (tid == 0) sred[0] = r;
    }
    __syncthreads();
    const float inv = 1.0f / sred[0];

    {
        int t = 0;
        for (int j = tid; j < L; j += 256) row[j] = v[t++] * inv;
    }
    for (int j = L + tid; j < N; j += 256) row[j] = 0.f;
}

// ================= add + LayerNorm ==========================================
__global__ __launch_bounds__(256)
void add_layernorm(const float* __restrict__ attn,
                   const float* __restrict__ emb,
                   const float* __restrict__ gamma,
                   const float* __restrict__ beta,
                   float* __restrict__ out)
{
    const int i   = blockIdx.x;
    const int tid = threadIdx.x;
    const int lane = tid & 31, wid = tid >> 5;
    const int off = i * DDIM + tid * 4;

    float4 a = *(const float4*)(attn + off);
    float4 e = *(const float4*)(emb + off);
    float v0 = a.x + e.x, v1 = a.y + e.y, v2 = a.z + e.z, v3 = a.w + e.w;

    __shared__ float s_sum[8], s_sq[8];

    float sum = v0 + v1 + v2 + v3;
    float sq  = v0 * v0 + v1 * v1 + v2 * v2 + v3 * v3;
#pragma unroll
    for (int o = 16; o > 0; o >>= 1) {
        sum += __shfl_xor_sync(0xffffffffu, sum, o);
        sq  += __shfl_xor_sync(0xffffffffu, sq, o);
    }
    if (lane == 0) { s_sum[wid] = sum; s_sq[wid] = sq; }
    __syncthreads();
    if (tid < 32) {
        float r1 = (tid < 8) ? s_sum[tid] : 0.f;
        float r2 = (tid < 8) ? s_sq[tid]  : 0.f;
#pragma unroll
        for (int o = 4; o > 0; o >>= 1) {
            r1 += __shfl_xor_sync(0xffffffffu, r1, o);
            r2 += __shfl_xor_sync(0xffffffffu, r2, o);
        }
        if (tid == 0) { s_sum[0] = r1; s_sq[0] = r2; }
    }
    __syncthreads();
    const float mu   = s_sum[0] * (1.0f / DDIM);
    const float var  = s_sq[0] * (1.0f / DDIM) - mu * mu;
    const float rstd = rsqrtf(var + 1e-5f);

    const int c = tid * 4;
    float4 g = *(const float4*)(gamma + c);
    float4 b = *(const float4*)(beta + c);
    float4 o4;
    o4.x = (v0 - mu) * rstd * g.x + b.x;
    o4.y = (v1 - mu) * rstd * g.y + b.y;
    o4.z = (v2 - mu) * rstd * g.z + b.z;
    o4.w = (v3 - mu) * rstd * g.w + b.w;
    *(float4*)(out + off) = o4;
}

// ============================================================================
extern "C" void kernel_launch(void* const* d_in, const int* in_sizes, int n_in,
                              void* d_out, int out_size)
{
    const float* emb   = (const float*)d_in[0];
    const float* Wq    = (const float*)d_in[1];
    const float* bq    = (const float*)d_in[2];
    const float* Wk    = (const float*)d_in[3];
    const float* bk    = (const float*)d_in[4];
    const float* Wv    = (const float*)d_in[5];
    const float* bv    = (const float*)d_in[6];
    const float* gamma = (const float*)d_in[7];
    const float* beta  = (const float*)d_in[8];
    const float* W1    = (const float*)d_in[9];
    const float* b1    = (const float*)d_in[10];
    const float* W2    = (const float*)d_in[11];
    const float* b2    = (const float*)d_in[12];
    float* out = (float*)d_out;

    float *Q, *K, *V, *S, *X, *H;
    cudaGetSymbolAddress((void**)&Q, g_Q);
    cudaGetSymbolAddress((void**)&K, g_K);
    cudaGetSymbolAddress((void**)&V, g_V);
    cudaGetSymbolAddress((void**)&S, g_S);
    cudaGetSymbolAddress((void**)&X, g_X);
    cudaGetSymbolAddress((void**)&H, g_H);

    __nv_bfloat16 *Wqt_h, *Wqt_l, *Wkt_h, *Wkt_l, *Wvt_h, *Wvt_l;
    __nv_bfloat16 *W1t_h, *W1t_l, *W2t_h, *W2t_l, *Vt_h, *Vt_l;
    cudaGetSymbolAddress((void**)&Wqt_h, g_Wqt_h);
    cudaGetSymbolAddress((void**)&Wqt_l, g_Wqt_l);
    cudaGetSymbolAddress((void**)&Wkt_h, g_Wkt_h);
    cudaGetSymbolAddress((void**)&Wkt_l, g_Wkt_l);
    cudaGetSymbolAddress((void**)&Wvt_h, g_Wvt_h);
    cudaGetSymbolAddress((void**)&Wvt_l, g_Wvt_l);
    cudaGetSymbolAddress((void**)&W1t_h, g_W1t_h);
    cudaGetSymbolAddress((void**)&W1t_l, g_W1t_l);
    cudaGetSymbolAddress((void**)&W2t_h, g_W2t_h);
    cudaGetSymbolAddress((void**)&W2t_l, g_W2t_l);
    cudaGetSymbolAddress((void**)&Vt_h, g_Vt_h);
    cudaGetSymbolAddress((void**)&Vt_l, g_Vt_l);

    cudaFuncSetAttribute(mma_gemm<1, 0, 0, 0, 0>, cudaFuncAttributeMaxDynamicSharedMemorySize, SM_BYTES);
    cudaFuncSetAttribute(mma_gemm<0, 0, 1, 1, 0>, cudaFuncAttributeMaxDynamicSharedMemorySize, SM_BYTES);
    cudaFuncSetAttribute(mma_gemm<0, 0, 0, 0, 1>, cudaFuncAttributeMaxDynamicSharedMemorySize, SM_BYTES);
    cudaFuncSetAttribute(mma_gemm<1, 1, 0, 0, 0>, cudaFuncAttributeMaxDynamicSharedMemorySize, SM_BYTES);

    const dim3 blk(256);
    const dim3 grid_nd(DDIM / 128, NTOK / 128);   // (8, 32)
    const dim3 grid_nn(NTOK / 128, NTOK / 128);   // (32, 32)
    const dim3 tblk(256);

    // ---- prep: transpose + split weights ----
    transpose_split<<<dim3(DDIM / 32, DDIM / 32), tblk>>>(Wq, DDIM, DDIM, Wqt_h, Wqt_l);
    transpose_split<<<dim3(DDIM / 32, DDIM / 32), tblk>>>(Wk, DDIM, DDIM, Wkt_h, Wkt_l);
    transpose_split<<<dim3(DDIM / 32, DDIM / 32), tblk>>>(Wv, DDIM, DDIM, Wvt_h, Wvt_l);
    transpose_split<<<dim3(FDIM / 32, DDIM / 32), tblk>>>(W1, DDIM, FDIM, W1t_h, W1t_l);
    transpose_split<<<dim3(DDIM / 32, FDIM / 32), tblk>>>(W2, FDIM, DDIM, W2t_h, W2t_l);

    // ---- QKV projections ----
    mma_gemm<1, 0, 0, 0, 0><<<grid_nd, blk, SM_BYTES>>>(NTOK, DDIM, DDIM, emb, Wqt_h, Wqt_l, nullptr, bq, Q, 1.0f);
    mma_gemm<1, 0, 0, 0, 0><<<grid_nd, blk, SM_BYTES>>>(NTOK, DDIM, DDIM, emb, Wkt_h, Wkt_l, nullptr, bk, K, 1.0f);
    mma_gemm<1, 0, 0, 0, 0><<<grid_nd, blk, SM_BYTES>>>(NTOK, DDIM, DDIM, emb, Wvt_h, Wvt_l, nullptr, bv, V, 1.0f);

    // V^T for the A@V GEMM
    transpose_split<<<dim3(DDIM / 32, NTOK / 32), tblk>>>(V, NTOK, DDIM, Vt_h, Vt_l);

    // ---- attention scores (B = K matrix fp32 K-major; causal tile skip) ----
    mma_gemm<0, 0, 1, 1, 0><<<grid_nn, blk, SM_BYTES>>>(NTOK, NTOK, DDIM, Q, nullptr, nullptr, K, nullptr, S, 1.0f / 32.0f);
    causal_softmax<<<NTOK, blk>>>(S, NTOK);

    // ---- A @ V (causal K-limit) ----
    mma_gemm<0, 0, 0, 0, 1><<<grid_nd, blk, SM_BYTES>>>(NTOK, DDIM, NTOK, S, Vt_h, Vt_l, nullptr, nullptr, X, 1.0f);

    // ---- add + layernorm ----
    add_layernorm<<<NTOK, blk>>>(X, emb, gamma, beta, X);

    // ---- FFN ----
    mma_gemm<1, 1, 0, 0, 0><<<grid_nn, blk, SM_BYTES>>>(NTOK, FDIM, DDIM, X, W1t_h, W1t_l, nullptr, b1, H, 1.0f);
    mma_gemm<1, 0, 0, 0, 0><<<grid_nd, blk, SM_BYTES>>>(NTOK, DDIM, FDIM, H, W2t_h, W2t_l, nullptr, b2, out, 1.0f);
}